// round 4
// baseline (speedup 1.0000x reference)
#include <cuda_runtime.h>
#include <math.h>

// Problem constants
#define N_    4096
#define D_    640
#define H_    4
#define E_    16
#define NOUT_ 2048
#define HE_   64         // H_*E_
#define SPLITS  8        // attention key-axis splits
#define SPLITD  8        // downsample K splits

// ---------------------------------------------------------------------------
// Device scratch (no allocations allowed)
// ---------------------------------------------------------------------------
__device__ float g_q [H_*N_*E_];
__device__ float g_k [H_*N_*E_];
__device__ float g_v [H_*N_*E_];
__device__ float g_pm[SPLITS*H_*N_];
__device__ float g_pl[SPLITS*H_*N_];
__device__ float g_po[SPLITS*H_*N_*E_];
__device__ float g_vc[N_*HE_];                 // concatenated heads [N][H*E]
__device__ float g_dp[SPLITD*NOUT_*HE_];       // downsample split-K partials

// ---------------------------------------------------------------------------
// Kernel 1: fused QKV projection.
//   out[n, c] = sum_d x[n,d] * W[c,d] + b[c], c = h*E+e, for sel in {q,k,v}
//   Stored as g_{q,k,v}[(h*N + n)*E + e].
// Tile: 64 tokens x 64 cols, BK=16, 256 threads, 4x4 microtile.
// ---------------------------------------------------------------------------
__global__ void qkv_kernel(const float* __restrict__ x,
                           const float* __restrict__ Wq, const float* __restrict__ bq,
                           const float* __restrict__ Wk, const float* __restrict__ bk,
                           const float* __restrict__ Wv, const float* __restrict__ bv)
{
    const int sel = blockIdx.y;                 // 0=q 1=k 2=v
    const float* __restrict__ W = (sel == 0) ? Wq : (sel == 1) ? Wk : Wv;
    const float* __restrict__ b = (sel == 0) ? bq : (sel == 1) ? bk : bv;
    float* __restrict__ dst     = (sel == 0) ? g_q : (sel == 1) ? g_k : g_v;

    const int m0  = blockIdx.x * 64;
    const int tid = threadIdx.x;
    const int tx  = tid & 15;                   // col group (x4)
    const int ty  = tid >> 4;                   // row group (x4)

    __shared__ float Xs[16][68];                // [k][token], pad 68 to dodge conflicts
    __shared__ float Ws[16][68];                // [k][col]

    float acc[4][4];
#pragma unroll
    for (int i = 0; i < 4; ++i)
#pragma unroll
        for (int j = 0; j < 4; ++j) acc[i][j] = 0.f;

    const int lk = tid & 15;                    // loader: k index
    const int lr = tid >> 4;                    // loader: base row (0..15)

    for (int k0 = 0; k0 < D_; k0 += 16) {
        __syncthreads();
#pragma unroll
        for (int p = 0; p < 4; ++p) {
            int r = lr + p * 16;
            Xs[lk][r] = x[(m0 + r) * D_ + k0 + lk];
            Ws[lk][r] = W[r * D_ + k0 + lk];    // r = output col (h*E+e)
        }
        __syncthreads();
#pragma unroll
        for (int kk = 0; kk < 16; ++kk) {
            float4 a = *(const float4*)&Xs[kk][ty * 4];
            float4 bb = *(const float4*)&Ws[kk][tx * 4];
            acc[0][0] += a.x * bb.x; acc[0][1] += a.x * bb.y; acc[0][2] += a.x * bb.z; acc[0][3] += a.x * bb.w;
            acc[1][0] += a.y * bb.x; acc[1][1] += a.y * bb.y; acc[1][2] += a.y * bb.z; acc[1][3] += a.y * bb.w;
            acc[2][0] += a.z * bb.x; acc[2][1] += a.z * bb.y; acc[2][2] += a.z * bb.z; acc[2][3] += a.z * bb.w;
            acc[3][0] += a.w * bb.x; acc[3][1] += a.w * bb.y; acc[3][2] += a.w * bb.z; acc[3][3] += a.w * bb.w;
        }
    }

#pragma unroll
    for (int i = 0; i < 4; ++i) {
        int n = m0 + ty * 4 + i;
#pragma unroll
        for (int j = 0; j < 4; ++j) {
            int c = tx * 4 + j;
            int h = c >> 4, e = c & 15;
            dst[(h * N_ + n) * E_ + e] = acc[i][j] + b[c];
        }
    }
}

// ---------------------------------------------------------------------------
// Kernel 2: flash-decoding attention partials.
//   grid (N/128, H, SPLITS), block 128 (one query row per thread).
//   Each block scans N/SPLITS keys with online softmax; writes (m, l, o[16]).
// ---------------------------------------------------------------------------
__global__ void attn_kernel()
{
    const int tid = threadIdx.x;
    const int h   = blockIdx.y;
    const int sp  = blockIdx.z;
    const int row = blockIdx.x * 128 + tid;

    __shared__ float4 ks[32][4];
    __shared__ float4 vs[32][4];

    const float4* __restrict__ qg = (const float4*)g_q;
    const float4* __restrict__ kg = (const float4*)g_k;
    const float4* __restrict__ vg = (const float4*)g_v;

    const float scale = 0.25f;                  // 1/sqrt(E)
    float4 q0 = qg[(h * N_ + row) * 4 + 0];
    float4 q1 = qg[(h * N_ + row) * 4 + 1];
    float4 q2 = qg[(h * N_ + row) * 4 + 2];
    float4 q3 = qg[(h * N_ + row) * 4 + 3];
    q0.x *= scale; q0.y *= scale; q0.z *= scale; q0.w *= scale;
    q1.x *= scale; q1.y *= scale; q1.z *= scale; q1.w *= scale;
    q2.x *= scale; q2.y *= scale; q2.z *= scale; q2.w *= scale;
    q3.x *= scale; q3.y *= scale; q3.z *= scale; q3.w *= scale;

    float m = -INFINITY, l = 0.f;
    float4 o0 = {0,0,0,0}, o1 = {0,0,0,0}, o2 = {0,0,0,0}, o3 = {0,0,0,0};

    const int lr = tid >> 2;                    // loader row (0..31)
    const int lc = tid & 3;                     // loader float4 idx
    const int kbeg = sp * (N_ / SPLITS);
    const int kend = kbeg + (N_ / SPLITS);

    for (int k0 = kbeg; k0 < kend; k0 += 32) {
        __syncthreads();
        ks[lr][lc] = kg[(h * N_ + k0 + lr) * 4 + lc];
        vs[lr][lc] = vg[(h * N_ + k0 + lr) * 4 + lc];
        __syncthreads();

        float s[32];
#pragma unroll
        for (int j = 0; j < 32; ++j) {
            float4 a = ks[j][0], b = ks[j][1], c = ks[j][2], d = ks[j][3];
            s[j] = q0.x*a.x + q0.y*a.y + q0.z*a.z + q0.w*a.w
                 + q1.x*b.x + q1.y*b.y + q1.z*b.z + q1.w*b.w
                 + q2.x*c.x + q2.y*c.y + q2.z*c.z + q2.w*c.w
                 + q3.x*d.x + q3.y*d.y + q3.z*d.z + q3.w*d.w;
        }

        float mn = m;
#pragma unroll
        for (int j = 0; j < 32; ++j) mn = fmaxf(mn, s[j]);

        float corr = __expf(m - mn);            // m=-inf first pass -> 0
        l *= corr;
        o0.x *= corr; o0.y *= corr; o0.z *= corr; o0.w *= corr;
        o1.x *= corr; o1.y *= corr; o1.z *= corr; o1.w *= corr;
        o2.x *= corr; o2.y *= corr; o2.z *= corr; o2.w *= corr;
        o3.x *= corr; o3.y *= corr; o3.z *= corr; o3.w *= corr;

#pragma unroll
        for (int j = 0; j < 32; ++j) {
            float p = __expf(s[j] - mn);
            l += p;
            float4 a = vs[j][0], b = vs[j][1], c = vs[j][2], d = vs[j][3];
            o0.x += p * a.x; o0.y += p * a.y; o0.z += p * a.z; o0.w += p * a.w;
            o1.x += p * b.x; o1.y += p * b.y; o1.z += p * b.z; o1.w += p * b.w;
            o2.x += p * c.x; o2.y += p * c.y; o2.z += p * c.z; o2.w += p * c.w;
            o3.x += p * d.x; o3.y += p * d.y; o3.z += p * d.z; o3.w += p * d.w;
        }
        m = mn;
    }

    const int base = (sp * H_ + h) * N_ + row;
    g_pm[base] = m;
    g_pl[base] = l;
    float4* __restrict__ pog = (float4*)g_po;
    pog[base * 4 + 0] = o0;
    pog[base * 4 + 1] = o1;
    pog[base * 4 + 2] = o2;
    pog[base * 4 + 3] = o3;
}

// ---------------------------------------------------------------------------
// Kernel 3: combine split partials, add residual v, write concat layout.
//   g_vc[n*64 + h*16 + e] = v[h,n,e] + (sum_sp w_sp * o_sp) / (sum_sp w_sp*l_sp)
// ---------------------------------------------------------------------------
__global__ void combine_kernel()
{
    const int t = blockIdx.x * 128 + threadIdx.x;   // [0, H*N)
    if (t >= H_ * N_) return;
    const int h = t / N_;
    const int n = t % N_;

    float m = -INFINITY;
#pragma unroll
    for (int sp = 0; sp < SPLITS; ++sp)
        m = fmaxf(m, g_pm[(sp * H_ + h) * N_ + n]);

    float l = 0.f;
    float4 o0 = {0,0,0,0}, o1 = {0,0,0,0}, o2 = {0,0,0,0}, o3 = {0,0,0,0};
    const float4* __restrict__ pog = (const float4*)g_po;
#pragma unroll
    for (int sp = 0; sp < SPLITS; ++sp) {
        int base = (sp * H_ + h) * N_ + n;
        float w = __expf(g_pm[base] - m);
        l += g_pl[base] * w;
        float4 a = pog[base * 4 + 0], b = pog[base * 4 + 1];
        float4 c = pog[base * 4 + 2], d = pog[base * 4 + 3];
        o0.x += w * a.x; o0.y += w * a.y; o0.z += w * a.z; o0.w += w * a.w;
        o1.x += w * b.x; o1.y += w * b.y; o1.z += w * b.z; o1.w += w * b.w;
        o2.x += w * c.x; o2.y += w * c.y; o2.z += w * c.z; o2.w += w * c.w;
        o3.x += w * d.x; o3.y += w * d.y; o3.z += w * d.z; o3.w += w * d.w;
    }
    const float inv = 1.f / l;

    const float4* __restrict__ vg = (const float4*)g_v;
    float4 v0 = vg[(h * N_ + n) * 4 + 0];
    float4 v1 = vg[(h * N_ + n) * 4 + 1];
    float4 v2 = vg[(h * N_ + n) * 4 + 2];
    float4 v3 = vg[(h * N_ + n) * 4 + 3];

    float4 r0 = { v0.x + o0.x * inv, v0.y + o0.y * inv, v0.z + o0.z * inv, v0.w + o0.w * inv };
    float4 r1 = { v1.x + o1.x * inv, v1.y + o1.y * inv, v1.z + o1.z * inv, v1.w + o1.w * inv };
    float4 r2 = { v2.x + o2.x * inv, v2.y + o2.y * inv, v2.z + o2.z * inv, v2.w + o2.w * inv };
    float4 r3 = { v3.x + o3.x * inv, v3.y + o3.y * inv, v3.z + o3.z * inv, v3.w + o3.w * inv };

    float4* __restrict__ vcg = (float4*)g_vc;
    vcg[n * 16 + h * 4 + 0] = r0;
    vcg[n * 16 + h * 4 + 1] = r1;
    vcg[n * 16 + h * 4 + 2] = r2;
    vcg[n * 16 + h * 4 + 3] = r3;
}

// ---------------------------------------------------------------------------
// Kernel 4: downsample GEMM, split-K partials.
//   g_dp[sp][m][c] = sum_{k in chunk sp} Wd[m,k] * Vcat[k,c]
//   grid (NOUT/128, SPLITD), block 256, 8x4 microtile, BK=32.
// ---------------------------------------------------------------------------
__global__ void down_kernel(const float* __restrict__ Wd)
{
    const int m0   = blockIdx.x * 128;
    const int sp   = blockIdx.y;
    const int kbeg = sp * (N_ / SPLITD);        // 512-wide K chunk
    const int tid  = threadIdx.x;
    const int tx   = tid & 15;                  // col group (x4)
    const int ty   = tid >> 4;                  // row group (x8)

    __shared__ float Wds[32][129];              // [k][m], stride 129: conflict-free
    __shared__ float Vs [32][64];               // [k][c]

    float acc[8][4];
#pragma unroll
    for (int i = 0; i < 8; ++i)
#pragma unroll
        for (int j = 0; j < 4; ++j) acc[i][j] = 0.f;

    const int wlk = tid & 31;                   // Wd loader: k
    const int wlr = tid >> 5;                   // Wd loader: row base (0..7)
    const int vlc = tid & 63;                   // V loader: col
    const int vlr = tid >> 6;                   // V loader: row base (0..3)

    for (int kt = 0; kt < N_ / SPLITD; kt += 32) {
        __syncthreads();
#pragma unroll
        for (int p = 0; p < 16; ++p) {
            int r = wlr + p * 8;
            Wds[wlk][r] = Wd[(m0 + r) * N_ + kbeg + kt + wlk];
        }
#pragma unroll
        for (int p = 0; p < 8; ++p) {
            int r = vlr + p * 4;
            Vs[r][vlc] = g_vc[(kbeg + kt + r) * HE_ + vlc];
        }
        __syncthreads();

#pragma unroll 4
        for (int kk = 0; kk < 32; ++kk) {
            float4 bb = *(const float4*)&Vs[kk][tx * 4];
            float a[8];
#pragma unroll
            for (int i = 0; i < 8; ++i) a[i] = Wds[kk][ty * 8 + i];
#pragma unroll
            for (int i = 0; i < 8; ++i) {
                acc[i][0] += a[i] * bb.x;
                acc[i][1] += a[i] * bb.y;
                acc[i][2] += a[i] * bb.z;
                acc[i][3] += a[i] * bb.w;
            }
        }
    }

    float4* __restrict__ dp4 = (float4*)g_dp;
#pragma unroll
    for (int i = 0; i < 8; ++i) {
        int m = m0 + ty * 8 + i;
        float4 r = { acc[i][0], acc[i][1], acc[i][2], acc[i][3] };
        dp4[(sp * NOUT_ + m) * 16 + tx] = r;
    }
}

// ---------------------------------------------------------------------------
// Kernel 5: reduce split-K partials + bias -> final output [NOUT, 64].
// ---------------------------------------------------------------------------
__global__ void dreduce_kernel(const float* __restrict__ bd, float* __restrict__ out)
{
    const int t = blockIdx.x * 256 + threadIdx.x;   // float4 index, [0, NOUT*64/4)
    if (t >= NOUT_ * HE_ / 4) return;
    const int m = t >> 4;                            // row
    float bias = bd[m];
    float4 acc = { bias, bias, bias, bias };
    const float4* __restrict__ dp4 = (const float4*)g_dp;
#pragma unroll
    for (int sp = 0; sp < SPLITD; ++sp) {
        float4 p = dp4[sp * (NOUT_ * 16) + t];
        acc.x += p.x; acc.y += p.y; acc.z += p.z; acc.w += p.w;
    }
    ((float4*)out)[t] = acc;
}

// ---------------------------------------------------------------------------
extern "C" void kernel_launch(void* const* d_in, const int* in_sizes, int n_in,
                              void* d_out, int out_size)
{
    const float* x  = (const float*)d_in[0];
    const float* Wq = (const float*)d_in[1];
    const float* bq = (const float*)d_in[2];
    const float* Wk = (const float*)d_in[3];
    const float* bk = (const float*)d_in[4];
    const float* Wv = (const float*)d_in[5];
    const float* bv = (const float*)d_in[6];
    const float* Wd = (const float*)d_in[7];
    const float* bd = (const float*)d_in[8];
    float* out = (float*)d_out;

    qkv_kernel<<<dim3(N_ / 64, 3), 256>>>(x, Wq, bq, Wk, bk, Wv, bv);
    attn_kernel<<<dim3(N_ / 128, H_, SPLITS), 128>>>();
    combine_kernel<<<(H_ * N_) / 128, 128>>>();
    down_kernel<<<dim3(NOUT_ / 128, SPLITD), 256>>>(Wd);
    dreduce_kernel<<<(NOUT_ * HE_ / 4 + 255) / 256, 256>>>(bd, out);
}